// round 1
// baseline (speedup 1.0000x reference)
#include <cuda_runtime.h>

#define NSTAGES 12
#define NPAIRS  2048
#define NCOLS   4096
#define NROWS   4096
#define RPC     8       // rows per CTA
#define TPB     512

// Precomputed (cos, sin) per stage/pair. __device__ global: no allocation.
__device__ float2 g_cs[NSTAGES * NPAIRS];

__global__ void cs_precompute(const float* __restrict__ ang) {
    int i = blockIdx.x * blockDim.x + threadIdx.x;
    if (i < NSTAGES * NPAIRS) {
        float s, c;
        sincosf(ang[i], &s, &c);
        g_cs[i] = make_float2(c, s);
    }
}

// Bank-conflict-free swizzle for all four exchange patterns (D = 1, 8, 64, 512).
// Injects word-address bits 5-7 into bits 0-2 and bits 6-7 into bits 3-4;
// provably bijective on the 5 lane-varying bits per LDS/STS instruction.
__device__ __forceinline__ int swz(int a) {
    return a ^ ((a >> 5) & 7) ^ (((a >> 6) & 3) << 3);
}

__device__ __forceinline__ void rot(float2 cs, float& a, float& b) {
    float a2 = cs.x * a - cs.y * b;
    float b2 = cs.y * a + cs.x * b;
    a = a2;
    b = b2;
}

// Group K handles stages s = 3K..3K+2 (dist = D, 2D, 4D with D = 8^K)
// entirely in registers. Thread holds elements n = blk*8D + off + D*j, j=0..7.
// For all three stages, the 4 needed angle indices are base_p + m*D with
// base_p = blk*4D + off (derivation in analysis).
template<int K>
__device__ __forceinline__ void do_group(float* sm, const float* __restrict__ gx,
                                         float* __restrict__ gy, int t, long rowBase) {
    const int D      = 1 << (3 * K);
    const int off    = t & (D - 1);
    const int blk    = t >> (3 * K);
    const int base_n = blk * 8 * D + off;
    const int base_p = blk * 4 * D + off;

    float2 cs[3][4];
#pragma unroll
    for (int u = 0; u < 3; u++) {
#pragma unroll
        for (int m = 0; m < 4; m++) {
            cs[u][m] = g_cs[(3 * K + u) * NPAIRS + base_p + m * D];
        }
    }

#pragma unroll 1
    for (int r = 0; r < RPC; r++) {
        float v[8];
        float* smr = sm + r * NCOLS;

        if (K == 0) {
            // canonical contiguous: 2x float4 loads, fully coalesced
            const float4* p =
                reinterpret_cast<const float4*>(gx + rowBase + (long)r * NCOLS + 8 * t);
            float4 f0 = __ldg(p);
            float4 f1 = __ldg(p + 1);
            v[0] = f0.x; v[1] = f0.y; v[2] = f0.z; v[3] = f0.w;
            v[4] = f1.x; v[5] = f1.y; v[6] = f1.z; v[7] = f1.w;
        } else {
#pragma unroll
            for (int j = 0; j < 8; j++)
                v[j] = smr[swz(base_n + D * j)];
        }

        // stage u=0 (dist = D): pairs (2m, 2m+1)
#pragma unroll
        for (int m = 0; m < 4; m++) rot(cs[0][m], v[2 * m], v[2 * m + 1]);

        // stage u=1 (dist = 2D): pairs (j, j+2), j in {0,1,4,5}
#pragma unroll
        for (int m = 0; m < 4; m++) {
            int j = ((m >> 1) << 2) | (m & 1);
            rot(cs[1][m], v[j], v[j + 2]);
        }

        // stage u=2 (dist = 4D): pairs (m, m+4)
#pragma unroll
        for (int m = 0; m < 4; m++) rot(cs[2][m], v[m], v[m + 4]);

        if (K == 3) {
            // n = t + 512*j: consecutive lanes -> consecutive addresses, coalesced
#pragma unroll
            for (int j = 0; j < 8; j++)
                gy[rowBase + (long)r * NCOLS + t + 512 * j] = v[j];
        } else {
#pragma unroll
            for (int j = 0; j < 8; j++)
                smr[swz(base_n + D * j)] = v[j];
        }
    }
}

__global__ void __launch_bounds__(TPB, 1)
butterfly_kernel(const float* __restrict__ x, float* __restrict__ y) {
    extern __shared__ float sm[];   // RPC * NCOLS floats = 128 KB
    int t = threadIdx.x;
    long rowBase = (long)blockIdx.x * RPC * NCOLS;

    do_group<0>(sm, x, y, t, rowBase);   // global -> regs, stages 0-2, -> smem
    __syncthreads();
    do_group<1>(sm, x, y, t, rowBase);   // smem -> regs, stages 3-5, -> smem
    __syncthreads();
    do_group<2>(sm, x, y, t, rowBase);   // smem -> regs, stages 6-8, -> smem
    __syncthreads();
    do_group<3>(sm, x, y, t, rowBase);   // smem -> regs, stages 9-11, -> global
}

extern "C" void kernel_launch(void* const* d_in, const int* in_sizes, int n_in,
                              void* d_out, int out_size) {
    const float* x   = (const float*)d_in[0];
    const float* ang = (const float*)d_in[1];
    float* y         = (float*)d_out;

    (void)in_sizes; (void)n_in; (void)out_size;

    cudaFuncSetAttribute(butterfly_kernel,
                         cudaFuncAttributeMaxDynamicSharedMemorySize,
                         RPC * NCOLS * (int)sizeof(float));

    cs_precompute<<<(NSTAGES * NPAIRS + 255) / 256, 256>>>(ang);
    butterfly_kernel<<<NROWS / RPC, TPB, RPC * NCOLS * sizeof(float)>>>(x, y);
}

// round 2
// speedup vs baseline: 1.3131x; 1.3131x over previous
#include <cuda_runtime.h>

#define NSTAGES 12
#define NPAIRS  2048
#define NCOLS   4096
#define NROWS   4096
#define RPC     4       // rows per CTA (was 8) -> 64 KB smem -> 2 CTAs/SM
#define TPB     512

// Precomputed (cos, sin) per stage/pair. __device__ global: no allocation.
__device__ float2 g_cs[NSTAGES * NPAIRS];

__global__ void cs_precompute(const float* __restrict__ ang) {
    int i = blockIdx.x * blockDim.x + threadIdx.x;
    if (i < NSTAGES * NPAIRS) {
        float s, c;
        sincosf(ang[i], &s, &c);
        g_cs[i] = make_float2(c, s);
    }
}

// Bank-conflict-free swizzle for all four exchange patterns (D = 1, 8, 64, 512).
__device__ __forceinline__ int swz(int a) {
    return a ^ ((a >> 5) & 7) ^ (((a >> 6) & 3) << 3);
}

__device__ __forceinline__ void rot(float2 cs, float& a, float& b) {
    float a2 = cs.x * a - cs.y * b;
    float b2 = cs.y * a + cs.x * b;
    a = a2;
    b = b2;
}

// Group K handles stages s = 3K..3K+2 (dist = D, 2D, 4D with D = 8^K)
// entirely in registers. Thread holds elements n = blk*8D + off + D*j, j=0..7.
template<int K>
__device__ __forceinline__ void do_group(float* sm, const float* __restrict__ gx,
                                         float* __restrict__ gy, int t, long rowBase) {
    const int D      = 1 << (3 * K);
    const int off    = t & (D - 1);
    const int blk    = t >> (3 * K);
    const int base_n = blk * 8 * D + off;
    const int base_p = blk * 4 * D + off;

    float2 cs[3][4];
#pragma unroll
    for (int u = 0; u < 3; u++) {
#pragma unroll
        for (int m = 0; m < 4; m++) {
            cs[u][m] = g_cs[(3 * K + u) * NPAIRS + base_p + m * D];
        }
    }

    // Fully unrolled over rows: lets ptxas front-batch the LDG.128 / LDS /
    // STG.128 streams for high MLP instead of serializing one row at a time.
#pragma unroll
    for (int r = 0; r < RPC; r++) {
        float v[8];
        float* smr = sm + r * NCOLS;

        if (K == 0) {
            const float4* p =
                reinterpret_cast<const float4*>(gx + rowBase + (long)r * NCOLS + 8 * t);
            float4 f0 = __ldg(p);
            float4 f1 = __ldg(p + 1);
            v[0] = f0.x; v[1] = f0.y; v[2] = f0.z; v[3] = f0.w;
            v[4] = f1.x; v[5] = f1.y; v[6] = f1.z; v[7] = f1.w;
        } else {
#pragma unroll
            for (int j = 0; j < 8; j++)
                v[j] = smr[swz(base_n + D * j)];
        }

        // stage u=0 (dist = D): pairs (2m, 2m+1)
#pragma unroll
        for (int m = 0; m < 4; m++) rot(cs[0][m], v[2 * m], v[2 * m + 1]);

        // stage u=1 (dist = 2D): pairs (j, j+2), j in {0,1,4,5}
#pragma unroll
        for (int m = 0; m < 4; m++) {
            int j = ((m >> 1) << 2) | (m & 1);
            rot(cs[1][m], v[j], v[j + 2]);
        }

        // stage u=2 (dist = 4D): pairs (m, m+4)
#pragma unroll
        for (int m = 0; m < 4; m++) rot(cs[2][m], v[m], v[m + 4]);

        if (K == 3) {
            // n = t + 512*j: consecutive lanes -> consecutive addresses, coalesced
#pragma unroll
            for (int j = 0; j < 8; j++)
                gy[rowBase + (long)r * NCOLS + t + 512 * j] = v[j];
        } else {
#pragma unroll
            for (int j = 0; j < 8; j++)
                smr[swz(base_n + D * j)] = v[j];
        }
    }
}

__global__ void __launch_bounds__(TPB, 2)
butterfly_kernel(const float* __restrict__ x, float* __restrict__ y) {
    extern __shared__ float sm[];   // RPC * NCOLS floats = 64 KB
    int t = threadIdx.x;
    long rowBase = (long)blockIdx.x * RPC * NCOLS;

    do_group<0>(sm, x, y, t, rowBase);   // global -> regs, stages 0-2, -> smem
    __syncthreads();
    do_group<1>(sm, x, y, t, rowBase);   // smem -> regs, stages 3-5, -> smem
    __syncthreads();
    do_group<2>(sm, x, y, t, rowBase);   // smem -> regs, stages 6-8, -> smem
    __syncthreads();
    do_group<3>(sm, x, y, t, rowBase);   // smem -> regs, stages 9-11, -> global
}

extern "C" void kernel_launch(void* const* d_in, const int* in_sizes, int n_in,
                              void* d_out, int out_size) {
    const float* x   = (const float*)d_in[0];
    const float* ang = (const float*)d_in[1];
    float* y         = (float*)d_out;

    (void)in_sizes; (void)n_in; (void)out_size;

    cudaFuncSetAttribute(butterfly_kernel,
                         cudaFuncAttributeMaxDynamicSharedMemorySize,
                         RPC * NCOLS * (int)sizeof(float));

    cs_precompute<<<(NSTAGES * NPAIRS + 255) / 256, 256>>>(ang);
    butterfly_kernel<<<NROWS / RPC, TPB, RPC * NCOLS * sizeof(float)>>>(x, y);
}